// round 9
// baseline (speedup 1.0000x reference)
#include <cuda_runtime.h>
#include <math.h>

#define B_  8
#define N_  2048
#define H_  4
#define DM  256
#define DH  64
#define OUT_ELEMS ((size_t)B_ * N_ * DM)

// Scratch (device globals: allocation-free rule)
__device__ float g_q [(size_t)B_*H_*N_*DH];
__device__ float g_kr[(size_t)B_*H_*N_*DH];
__device__ float g_v [(size_t)B_*H_*N_*DH];
__device__ float g_x [(size_t)B_*N_*DM];

// ---------------- packed f32x2 helpers (sm_103a FFMA2 path) ----------------
typedef unsigned long long u64;

__device__ __forceinline__ u64 pack2(float x, float y) {
    u64 r;
    asm("mov.b64 %0, {%1, %2};" : "=l"(r) : "r"(__float_as_uint(x)), "r"(__float_as_uint(y)));
    return r;
}
__device__ __forceinline__ float2 unpack2(u64 v) {
    unsigned lo, hi;
    asm("mov.b64 {%0, %1}, %2;" : "=r"(lo), "=r"(hi) : "l"(v));
    return make_float2(__uint_as_float(lo), __uint_as_float(hi));
}
__device__ __forceinline__ void ffma2(u64& d, u64 a, u64 b) {
    asm("fma.rn.f32x2 %0, %1, %2, %0;" : "+l"(d) : "l"(a), "l"(b));
}
__device__ __forceinline__ void mul2(u64& d, u64 a) {
    asm("mul.rn.f32x2 %0, %0, %1;" : "+l"(d) : "l"(a));
}

// ---------------------------------------------------------------------------
// Kernel 1: per-head projections (unchanged, passing).
// ---------------------------------------------------------------------------
__global__ __launch_bounds__(256) void proj_kernel(
    const float* __restrict__ Q, const float* __restrict__ K,
    const float* __restrict__ V, const float* __restrict__ R,
    const float* __restrict__ Wq, const float* __restrict__ bq,
    const float* __restrict__ Wk, const float* __restrict__ bk,
    const float* __restrict__ Wv, const float* __restrict__ bv,
    const float* __restrict__ Wr, const float* __restrict__ br)
{
    const int which = blockIdx.z;
    const int h     = blockIdx.y;
    const int row0  = blockIdx.x * 64;
    const int t  = threadIdx.x;
    const int tx = t & 15;
    const int ty = t >> 4;

    __shared__ float As[16][64];
    __shared__ float Bs[16][64];

    const float* A0; const float* W0;
    const float* A1 = nullptr; const float* W1 = nullptr;
    float* Cout;
    if (which == 0)      { A0 = Q; W0 = Wq; Cout = g_q;  }
    else if (which == 1) { A0 = K; W0 = Wk; A1 = R; W1 = Wr; Cout = g_kr; }
    else                 { A0 = V; W0 = Wv; Cout = g_v;  }

    float acc[4][4];
    #pragma unroll
    for (int r = 0; r < 4; ++r)
        #pragma unroll
        for (int c = 0; c < 4; ++c) acc[r][c] = 0.f;

    const int npass = (which == 1) ? 2 : 1;
    for (int pass = 0; pass < npass; ++pass) {
        const float* A = pass ? A1 : A0;
        const float* W = pass ? W1 : W0;
        for (int k0 = 0; k0 < DM; k0 += 16) {
            {
                const int ar = t >> 2, ac = (t & 3) * 4;
                float4 a4 = *(const float4*)(A + (size_t)(row0 + ar) * DM + k0 + ac);
                As[ac + 0][ar] = a4.x; As[ac + 1][ar] = a4.y;
                As[ac + 2][ar] = a4.z; As[ac + 3][ar] = a4.w;
            }
            {
                const int wd = t >> 4, wc = (t & 15) * 4;
                *(float4*)&Bs[wd][wc] =
                    *(const float4*)(W + (size_t)h * DM * DH + (size_t)(k0 + wd) * DH + wc);
            }
            __syncthreads();
            #pragma unroll
            for (int kk = 0; kk < 16; ++kk) {
                float4 af = *(float4*)&As[kk][ty * 4];
                float4 bf = *(float4*)&Bs[kk][tx * 4];
                float a[4] = {af.x, af.y, af.z, af.w};
                float b[4] = {bf.x, bf.y, bf.z, bf.w};
                #pragma unroll
                for (int r = 0; r < 4; ++r)
                    #pragma unroll
                    for (int c = 0; c < 4; ++c) acc[r][c] += a[r] * b[c];
            }
            __syncthreads();
        }
    }

    const float* bA = (which == 0) ? bq : (which == 1) ? bk : bv;
    float bias[4];
    #pragma unroll
    for (int c = 0; c < 4; ++c) {
        bias[c] = bA[h * DH + tx * 4 + c];
        if (which == 1) bias[c] += br[h * DH + tx * 4 + c];
    }
    #pragma unroll
    for (int r = 0; r < 4; ++r) {
        const int row = row0 + ty * 4 + r;
        const int b   = row >> 11;
        const int n   = row & (N_ - 1);
        float4 o = make_float4(acc[r][0] + bias[0], acc[r][1] + bias[1],
                               acc[r][2] + bias[2], acc[r][3] + bias[3]);
        *(float4*)(Cout + ((size_t)(b * H_ + h) * N_ + n) * DH + tx * 4) = o;
    }
}

// ---------------------------------------------------------------------------
// Kernel 2: flash attention with packed fma.rn.f32x2 (pairs over the
// reduction dim, so .lo sums even-k and .hi sums odd-k products).
//   q_int[dp][2i+e] = q[i][2dp+e] * 0.125
//   k_int[dp][2j+e] = kr[j][2dp+e]      (region reused as P[i][j] natural)
//   v_int[jp][2c+e] = v[2jp+e][c]
// Thread map: rows i = 4*ty+r, cols j/c = 4*tx+cc. All inner smem accesses
// are LDS.128 (two packed pairs per load). Exact fp32 math (reordered sums).
// ---------------------------------------------------------------------------
__global__ __launch_bounds__(256, 2) void attn_kernel(float* __restrict__ scores_out)
{
    __shared__ __align__(16) float q_int[32 * 128];   // 16 KB
    __shared__ __align__(16) float kp_s [32 * 128];   // 16 KB (k_int, then P)
    __shared__ __align__(16) float v_int[32 * 128];   // 16 KB

    const int qt = blockIdx.x;
    const int bh = blockIdx.y;
    const int t  = threadIdx.x;
    const int tx = t & 15, ty = t >> 4;
    const int ty4 = ty * 4, tx4 = tx * 4;

    const float* qptr  = g_q  + ((size_t)bh * N_ + (size_t)qt * 64) * DH;
    const float* krptr = g_kr + (size_t)bh * N_ * DH;
    const float* vptr  = g_v  + (size_t)bh * N_ * DH;
    float* sc = scores_out + (size_t)bh * N_ * N_ + (size_t)qt * 64 * N_;

    // build q_int once (d-pairs interleaved, pre-scaled by 1/8 exactly)
    {
        const int i = t >> 2;
        #pragma unroll
        for (int rep = 0; rep < 4; ++rep) {
            const int col = (t & 3) * 4 + rep * 16;   // multiple of 4
            float4 a = *(const float4*)(qptr + (size_t)i * DH + col);
            *(u64*)&q_int[(col >> 1) * 128 + 2 * i]       = pack2(a.x * 0.125f, a.y * 0.125f);
            *(u64*)&q_int[((col >> 1) + 1) * 128 + 2 * i] = pack2(a.z * 0.125f, a.w * 0.125f);
        }
    }

    float m_i[4], l_i[4];
    u64 o2[4][4];
    #pragma unroll
    for (int r = 0; r < 4; ++r) {
        m_i[r] = -INFINITY; l_i[r] = 0.f;
        #pragma unroll
        for (int c = 0; c < 4; ++c) o2[r][c] = 0ull;
    }

    for (int kt = 0; kt < N_ / 64; ++kt) {
        // ---- build k_int and v_int for this kv tile ----
        {
            const float* kp = krptr + (size_t)kt * 64 * DH;
            const float* vp = vptr  + (size_t)kt * 64 * DH;
            const int j  = t >> 2;
            const int jp = j >> 1, e = j & 1;
            #pragma unroll
            for (int rep = 0; rep < 4; ++rep) {
                const int col = (t & 3) * 4 + rep * 16;
                float4 a = *(const float4*)(kp + (size_t)j * DH + col);
                *(u64*)&kp_s[(col >> 1) * 128 + 2 * j]       = pack2(a.x, a.y);
                *(u64*)&kp_s[((col >> 1) + 1) * 128 + 2 * j] = pack2(a.z, a.w);
                float4 v4 = *(const float4*)(vp + (size_t)j * DH + col);
                v_int[jp * 128 + 2 * (col + 0) + e] = v4.x;
                v_int[jp * 128 + 2 * (col + 1) + e] = v4.y;
                v_int[jp * 128 + 2 * (col + 2) + e] = v4.z;
                v_int[jp * 128 + 2 * (col + 3) + e] = v4.w;
            }
        }
        __syncthreads();

        // ---- S = q @ kr^T, packed over d ----
        u64 s2[4][4];
        #pragma unroll
        for (int r = 0; r < 4; ++r)
            #pragma unroll
            for (int c = 0; c < 4; ++c) s2[r][c] = 0ull;

        #pragma unroll 8
        for (int dp = 0; dp < 32; ++dp) {
            ulonglong2 qa = *(ulonglong2*)&q_int[dp * 128 + 2 * ty4];       // rows ty4, ty4+1
            ulonglong2 qb = *(ulonglong2*)&q_int[dp * 128 + 2 * ty4 + 4];   // rows ty4+2, ty4+3
            ulonglong2 ka = *(ulonglong2*)&kp_s[dp * 128 + 2 * tx4];        // cols tx4, tx4+1
            ulonglong2 kb = *(ulonglong2*)&kp_s[dp * 128 + 2 * tx4 + 4];    // cols tx4+2, tx4+3
            u64 qv[4] = {qa.x, qa.y, qb.x, qb.y};
            u64 kv[4] = {ka.x, ka.y, kb.x, kb.y};
            #pragma unroll
            for (int r = 0; r < 4; ++r)
                #pragma unroll
                for (int c = 0; c < 4; ++c) ffma2(s2[r][c], qv[r], kv[c]);
        }

        // collapse pairs -> scalar scores; stream to global (cols tx4..tx4+3)
        float s[4][4];
        #pragma unroll
        for (int r = 0; r < 4; ++r) {
            #pragma unroll
            for (int c = 0; c < 4; ++c) {
                float2 f = unpack2(s2[r][c]);
                s[r][c] = f.x + f.y;
            }
            float4 sv = make_float4(s[r][0], s[r][1], s[r][2], s[r][3]);
            *(float4*)(sc + (size_t)(ty4 + r) * N_ + kt * 64 + tx4) = sv;
        }

        // ---- online softmax (row reduction over the 16 tx lanes) ----
        float corr[4];
        #pragma unroll
        for (int r = 0; r < 4; ++r) {
            float mx = fmaxf(fmaxf(s[r][0], s[r][1]), fmaxf(s[r][2], s[r][3]));
            #pragma unroll
            for (int off = 8; off > 0; off >>= 1)
                mx = fmaxf(mx, __shfl_xor_sync(0xffffffffu, mx, off));
            const float mnew = fmaxf(m_i[r], mx);
            corr[r] = __expf(m_i[r] - mnew);
            float rs = 0.f;
            #pragma unroll
            for (int c = 0; c < 4; ++c) {
                float p = __expf(s[r][c] - mnew);
                s[r][c] = p;
                rs += p;
            }
            #pragma unroll
            for (int off = 8; off > 0; off >>= 1)
                rs += __shfl_xor_sync(0xffffffffu, rs, off);
            l_i[r] = l_i[r] * corr[r] + rs;
            m_i[r] = mnew;
        }
        #pragma unroll
        for (int r = 0; r < 4; ++r) {
            u64 cd = pack2(corr[r], corr[r]);
            #pragma unroll
            for (int c = 0; c < 4; ++c) mul2(o2[r][c], cd);
        }

        __syncthreads();   // S reads of kp_s complete -> reuse as P

        // ---- P into shared (natural [i][j], float4 stores) ----
        #pragma unroll
        for (int r = 0; r < 4; ++r) {
            float4 pv = make_float4(s[r][0], s[r][1], s[r][2], s[r][3]);
            *(float4*)&kp_s[(ty4 + r) * 64 + tx4] = pv;
        }
        __syncthreads();

        // ---- O += P @ V, packed over j ----
        #pragma unroll 4
        for (int jp2 = 0; jp2 < 16; ++jp2) {
            // P pairs: rows ty4+r, j-pairs (4jp2,4jp2+1) and (4jp2+2,4jp2+3)
            ulonglong2 pv[4];
            #pragma unroll
            for (int r = 0; r < 4; ++r)
                pv[r] = *(ulonglong2*)&kp_s[(ty4 + r) * 64 + 4 * jp2];
            // V pairs for cols tx4..tx4+3, at jp = 2jp2 and 2jp2+1
            ulonglong2 va0 = *(ulonglong2*)&v_int[(2 * jp2 + 0) * 128 + 2 * tx4];
            ulonglong2 vb0 = *(ulonglong2*)&v_int[(2 * jp2 + 0) * 128 + 2 * tx4 + 4];
            ulonglong2 va1 = *(ulonglong2*)&v_int[(2 * jp2 + 1) * 128 + 2 * tx4];
            ulonglong2 vb1 = *(ulonglong2*)&v_int[(2 * jp2 + 1) * 128 + 2 * tx4 + 4];
            u64 v0[4] = {va0.x, va0.y, vb0.x, vb0.y};
            u64 v1[4] = {va1.x, va1.y, vb1.x, vb1.y};
            #pragma unroll
            for (int r = 0; r < 4; ++r)
                #pragma unroll
                for (int c = 0; c < 4; ++c) {
                    ffma2(o2[r][c], pv[r].x, v0[c]);
                    ffma2(o2[r][c], pv[r].y, v1[c]);
                }
        }
        __syncthreads();   // PV reads done before next tile overwrites
    }

    // finalize: O = (lo+hi)/l, write concat-head layout [B,N,256]
    const int b = bh >> 2;
    const int h = bh & 3;
    #pragma unroll
    for (int r = 0; r < 4; ++r) {
        const float inv = 1.f / l_i[r];
        const int n = qt * 64 + ty4 + r;
        float ov[4];
        #pragma unroll
        for (int c = 0; c < 4; ++c) {
            float2 f = unpack2(o2[r][c]);
            ov[c] = (f.x + f.y) * inv;
        }
        *(float4*)(g_x + ((size_t)b * N_ + n) * DM + h * DH + tx4) =
            make_float4(ov[0], ov[1], ov[2], ov[3]);
    }
}

// ---------------------------------------------------------------------------
// Kernel 3: out = x @ Wo^T + bo (unchanged, passing)
// ---------------------------------------------------------------------------
__global__ __launch_bounds__(256) void outproj_kernel(
    float* __restrict__ out, const float* __restrict__ Wo, const float* __restrict__ bo)
{
    const int o0   = blockIdx.y * 64;
    const int row0 = blockIdx.x * 64;
    const int t  = threadIdx.x;
    const int tx = t & 15, ty = t >> 4;

    __shared__ float As[16][64];
    __shared__ float Bs[16][64];

    float acc[4][4];
    #pragma unroll
    for (int r = 0; r < 4; ++r)
        #pragma unroll
        for (int c = 0; c < 4; ++c) acc[r][c] = 0.f;

    for (int k0 = 0; k0 < DM; k0 += 16) {
        {
            const int ar = t >> 2, ac = (t & 3) * 4;
            float4 a4 = *(const float4*)(g_x + (size_t)(row0 + ar) * DM + k0 + ac);
            As[ac + 0][ar] = a4.x; As[ac + 1][ar] = a4.y;
            As[ac + 2][ar] = a4.z; As[ac + 3][ar] = a4.w;
        }
        {
            const int oc = t >> 2, d4 = (t & 3) * 4;
            float4 w = *(const float4*)(Wo + (size_t)(o0 + oc) * DM + k0 + d4);
            Bs[d4 + 0][oc] = w.x; Bs[d4 + 1][oc] = w.y;
            Bs[d4 + 2][oc] = w.z; Bs[d4 + 3][oc] = w.w;
        }
        __syncthreads();
        #pragma unroll
        for (int kk = 0; kk < 16; ++kk) {
            float4 af = *(float4*)&As[kk][ty * 4];
            float4 bf = *(float4*)&Bs[kk][tx * 4];
            float a[4] = {af.x, af.y, af.z, af.w};
            float b[4] = {bf.x, bf.y, bf.z, bf.w};
            #pragma unroll
            for (int r = 0; r < 4; ++r)
                #pragma unroll
                for (int c = 0; c < 4; ++c) acc[r][c] += a[r] * b[c];
        }
        __syncthreads();
    }

    float bias[4];
    #pragma unroll
    for (int c = 0; c < 4; ++c) bias[c] = bo[o0 + tx * 4 + c];
    #pragma unroll
    for (int r = 0; r < 4; ++r) {
        const int row = row0 + ty * 4 + r;
        float4 o = make_float4(acc[r][0] + bias[0], acc[r][1] + bias[1],
                               acc[r][2] + bias[2], acc[r][3] + bias[3]);
        *(float4*)(out + (size_t)row * DM + o0 + tx * 4) = o;
    }
}

// ---------------------------------------------------------------------------
extern "C" void kernel_launch(void* const* d_in, const int* in_sizes, int n_in,
                              void* d_out, int out_size)
{
    const float* Q  = (const float*)d_in[0];
    const float* K  = (const float*)d_in[1];
    const float* V  = (const float*)d_in[2];
    const float* R  = (const float*)d_in[3];
    const float* Wq = (const float*)d_in[4];
    const float* bq = (const float*)d_in[5];
    const float* Wk = (const float*)d_in[6];
    const float* bk = (const float*)d_in[7];
    const float* Wv = (const float*)d_in[8];
    const float* bv = (const float*)d_in[9];
    const float* Wr = (const float*)d_in[10];
    const float* br = (const float*)d_in[11];
    const float* Wo = (const float*)d_in[12];
    const float* bo = (const float*)d_in[13];

    float* out    = (float*)d_out;            // [B,N,256]
    float* scores = out + OUT_ELEMS;          // [B,H,N,N]

    proj_kernel<<<dim3((B_ * N_) / 64, H_, 3), 256>>>(
        Q, K, V, R, Wq, bq, Wk, bk, Wv, bv, Wr, br);

    attn_kernel<<<dim3(N_ / 64, B_ * H_), 256>>>(scores);

    outproj_kernel<<<dim3((B_ * N_) / 64, DM / 64), 256>>>(out, Wo, bo);
}

// round 13
// speedup vs baseline: 2.0251x; 2.0251x over previous
#include <cuda_runtime.h>
#include <cuda_bf16.h>
#include <math.h>

#define B_  8
#define N_  2048
#define H_  4
#define DM  256
#define DH  64
#define OUT_ELEMS ((size_t)B_ * N_ * DM)

// Scratch (device globals: allocation-free rule)
__device__ float g_q [(size_t)B_*H_*N_*DH];   // [B,H,N,64]
__device__ float g_kr[(size_t)B_*H_*N_*DH];   // [B,H,N,64]
__device__ float g_v [(size_t)B_*H_*N_*DH];   // [B,H,N,64]
__device__ float g_x [(size_t)B_*N_*DM];      // [B,N,256]

// ======================= warp-mma helpers (baseline PTX) ====================
__device__ __forceinline__ unsigned smem_u32(const void* p) {
    return (unsigned)__cvta_generic_to_shared(p);
}
__device__ __forceinline__ void mma16816(float* c, const unsigned* a, const unsigned* b) {
    asm volatile(
        "mma.sync.aligned.m16n8k16.row.col.f32.bf16.bf16.f32 "
        "{%0,%1,%2,%3}, {%4,%5,%6,%7}, {%8,%9}, {%0,%1,%2,%3};"
        : "+f"(c[0]), "+f"(c[1]), "+f"(c[2]), "+f"(c[3])
        : "r"(a[0]), "r"(a[1]), "r"(a[2]), "r"(a[3]), "r"(b[0]), "r"(b[1]));
}
__device__ __forceinline__ void ldsm_x4(unsigned addr, unsigned* r) {
    asm volatile("ldmatrix.sync.aligned.m8n8.x4.shared.b16 {%0,%1,%2,%3}, [%4];"
        : "=r"(r[0]), "=r"(r[1]), "=r"(r[2]), "=r"(r[3]) : "r"(addr));
}
__device__ __forceinline__ void ldsm_x4_t(unsigned addr, unsigned* r) {
    asm volatile("ldmatrix.sync.aligned.m8n8.x4.trans.shared.b16 {%0,%1,%2,%3}, [%4];"
        : "=r"(r[0]), "=r"(r[1]), "=r"(r[2]), "=r"(r[3]) : "r"(addr));
}

// fp32 -> bf16 hi + bf16 lo split
__device__ __forceinline__ void split_bf16(float v, unsigned short& h, unsigned short& l) {
    __nv_bfloat16 hb = __float2bfloat16(v);
    __nv_bfloat16 lb = __float2bfloat16(v - __bfloat162float(hb));
    h = __bfloat16_as_ushort(hb);
    l = __bfloat16_as_ushort(lb);
}
// pack two fp32 into bf16x2 hi and lo (low half = first arg)
__device__ __forceinline__ void split2(float a, float b, unsigned& hi, unsigned& lo) {
    unsigned short ha, la, hb_, lb_;
    split_bf16(a, ha, la);
    split_bf16(b, hb_, lb_);
    hi = (unsigned)ha | ((unsigned)hb_ << 16);
    lo = (unsigned)la | ((unsigned)lb_ << 16);
}
// 8 consecutive fp32 -> uint4 hi + uint4 lo
__device__ __forceinline__ void pack8(const float* v, uint4& H, uint4& L) {
    split2(v[0], v[1], H.x, L.x);
    split2(v[2], v[3], H.y, L.y);
    split2(v[4], v[5], H.z, L.z);
    split2(v[6], v[7], H.w, L.w);
}

// ---------------------------------------------------------------------------
// Kernel 1: per-head projections (proven version, unchanged).
// ---------------------------------------------------------------------------
__global__ __launch_bounds__(256) void proj_kernel(
    const float* __restrict__ Q, const float* __restrict__ K,
    const float* __restrict__ V, const float* __restrict__ R,
    const float* __restrict__ Wq, const float* __restrict__ bq,
    const float* __restrict__ Wk, const float* __restrict__ bk,
    const float* __restrict__ Wv, const float* __restrict__ bv,
    const float* __restrict__ Wr, const float* __restrict__ br)
{
    const int which = blockIdx.z;
    const int h     = blockIdx.y;
    const int row0  = blockIdx.x * 64;
    const int t  = threadIdx.x;
    const int tx = t & 15;
    const int ty = t >> 4;

    __shared__ float As[16][64];
    __shared__ float Bs[16][64];

    const float* A0; const float* W0;
    const float* A1 = nullptr; const float* W1 = nullptr;
    float* Cout;
    if (which == 0)      { A0 = Q; W0 = Wq; Cout = g_q;  }
    else if (which == 1) { A0 = K; W0 = Wk; A1 = R; W1 = Wr; Cout = g_kr; }
    else                 { A0 = V; W0 = Wv; Cout = g_v;  }

    float acc[4][4];
    #pragma unroll
    for (int r = 0; r < 4; ++r)
        #pragma unroll
        for (int c = 0; c < 4; ++c) acc[r][c] = 0.f;

    const int npass = (which == 1) ? 2 : 1;
    for (int pass = 0; pass < npass; ++pass) {
        const float* A = pass ? A1 : A0;
        const float* W = pass ? W1 : W0;
        for (int k0 = 0; k0 < DM; k0 += 16) {
            {
                const int ar = t >> 2, ac = (t & 3) * 4;
                float4 a4 = *(const float4*)(A + (size_t)(row0 + ar) * DM + k0 + ac);
                As[ac + 0][ar] = a4.x; As[ac + 1][ar] = a4.y;
                As[ac + 2][ar] = a4.z; As[ac + 3][ar] = a4.w;
            }
            {
                const int wd = t >> 4, wc = (t & 15) * 4;
                *(float4*)&Bs[wd][wc] =
                    *(const float4*)(W + (size_t)h * DM * DH + (size_t)(k0 + wd) * DH + wc);
            }
            __syncthreads();
            #pragma unroll
            for (int kk = 0; kk < 16; ++kk) {
                float4 af = *(float4*)&As[kk][ty * 4];
                float4 bf = *(float4*)&Bs[kk][tx * 4];
                float a[4] = {af.x, af.y, af.z, af.w};
                float b[4] = {bf.x, bf.y, bf.z, bf.w};
                #pragma unroll
                for (int r = 0; r < 4; ++r)
                    #pragma unroll
                    for (int c = 0; c < 4; ++c) acc[r][c] += a[r] * b[c];
            }
            __syncthreads();
        }
    }

    const float* bA = (which == 0) ? bq : (which == 1) ? bk : bv;
    float bias[4];
    #pragma unroll
    for (int c = 0; c < 4; ++c) {
        bias[c] = bA[h * DH + tx * 4 + c];
        if (which == 1) bias[c] += br[h * DH + tx * 4 + c];
    }
    #pragma unroll
    for (int r = 0; r < 4; ++r) {
        const int row = row0 + ty * 4 + r;
        const int b   = row >> 11;
        const int n   = row & (N_ - 1);
        float4 o = make_float4(acc[r][0] + bias[0], acc[r][1] + bias[1],
                               acc[r][2] + bias[2], acc[r][3] + bias[3]);
        *(float4*)(Cout + ((size_t)(b * H_ + h) * N_ + n) * DH + tx * 4) = o;
    }
}

// ---------------------------------------------------------------------------
// Kernel 2: flash attention via warp-level bf16 mma.sync with hi/lo split.
//   CTA = 8 warps = 128 query rows (16/warp); kv tiles of 64 keys.
//   S = Qhi*Khi + Qlo*Khi + Qhi*Klo   (error ~2^-16, well under 1e-3)
//   O += Phi*Vhi + Plo*Vhi + Phi*Vlo  (P from S accumulators, FA2 reuse)
//   Raw scaled scores streamed to d_out from the C fragments.
// ---------------------------------------------------------------------------
__global__ __launch_bounds__(256, 1) void attn_mma_kernel(float* __restrict__ scores_out)
{
    __shared__ __nv_bfloat16 khi[64][72], klo[64][72];
    __shared__ __nv_bfloat16 vhi[64][72], vlo[64][72];

    const int t = threadIdx.x;
    const int w = t >> 5, lane = t & 31;
    const int g = lane >> 2, qq = lane & 3;     // C/A row group, col group
    const int qt = blockIdx.x, bh = blockIdx.y;

    const float* qbase = g_q  + ((size_t)bh * N_ + (size_t)qt * 128 + 16 * w) * DH;
    const float* kbase = g_kr + (size_t)bh * N_ * DH;
    const float* vbase = g_v  + (size_t)bh * N_ * DH;
    float* sc = scores_out + (size_t)bh * N_ * N_ + (size_t)(qt * 128) * N_;

    // ---- Q fragments (resident): 4 k-steps x 4 regs, hi and lo ----
    unsigned qhi[4][4], qlo[4][4];
    {
        const float* r0 = qbase + (size_t)g * DH;
        const float* r1 = qbase + (size_t)(g + 8) * DH;
        #pragma unroll
        for (int kk = 0; kk < 4; ++kk) {
            const int c = 16 * kk + 2 * qq;
            float2 v00 = *(const float2*)(r0 + c);
            float2 v10 = *(const float2*)(r1 + c);
            float2 v01 = *(const float2*)(r0 + c + 8);
            float2 v11 = *(const float2*)(r1 + c + 8);
            split2(v00.x * 0.125f, v00.y * 0.125f, qhi[kk][0], qlo[kk][0]);
            split2(v10.x * 0.125f, v10.y * 0.125f, qhi[kk][1], qlo[kk][1]);
            split2(v01.x * 0.125f, v01.y * 0.125f, qhi[kk][2], qlo[kk][2]);
            split2(v11.x * 0.125f, v11.y * 0.125f, qhi[kk][3], qlo[kk][3]);
        }
    }

    float oacc[8][4];
    #pragma unroll
    for (int nt = 0; nt < 8; ++nt)
        #pragma unroll
        for (int c = 0; c < 4; ++c) oacc[nt][c] = 0.f;
    float m0 = -INFINITY, m1 = -INFINITY, l0 = 0.f, l1 = 0.f;

    for (int kt = 0; kt < N_ / 64; ++kt) {
        // ---- fill K/V tile (64x64), hi/lo split ----
        {
            const int row = t >> 2, cq = (t & 3) * 16;
            const float* ks = kbase + ((size_t)kt * 64 + row) * DH + cq;
            const float* vs = vbase + ((size_t)kt * 64 + row) * DH + cq;
            float buf[8]; uint4 Hh, Ll;
            #pragma unroll
            for (int half = 0; half < 2; ++half) {
                const int c8 = cq + half * 8;
                float4 a = *(const float4*)(ks + half * 8);
                float4 b = *(const float4*)(ks + half * 8 + 4);
                buf[0]=a.x; buf[1]=a.y; buf[2]=a.z; buf[3]=a.w;
                buf[4]=b.x; buf[5]=b.y; buf[6]=b.z; buf[7]=b.w;
                pack8(buf, Hh, Ll);
                *(uint4*)&khi[row][c8] = Hh;
                *(uint4*)&klo[row][c8] = Ll;
                a = *(const float4*)(vs + half * 8);
                b = *(const float4*)(vs + half * 8 + 4);
                buf[0]=a.x; buf[1]=a.y; buf[2]=a.z; buf[3]=a.w;
                buf[4]=b.x; buf[5]=b.y; buf[6]=b.z; buf[7]=b.w;
                pack8(buf, Hh, Ll);
                *(uint4*)&vhi[row][c8] = Hh;
                *(uint4*)&vlo[row][c8] = Ll;
            }
        }
        __syncthreads();

        // ---- S = q @ kr^T : 16x64 per warp ----
        float sacc[8][4];
        #pragma unroll
        for (int nt = 0; nt < 8; ++nt)
            #pragma unroll
            for (int c = 0; c < 4; ++c) sacc[nt][c] = 0.f;

        const int l8 = lane & 7, grp = lane >> 3;
        #pragma unroll
        for (int kk = 0; kk < 4; ++kk) {
            unsigned bf[8][2];
            // Khi fragments for 8 n-tiles (keys)
            #pragma unroll
            for (int np = 0; np < 4; ++np) {
                const int key = 16 * np + l8 + ((grp & 2) ? 8 : 0);
                const int d   = 16 * kk + ((grp & 1) ? 8 : 0);
                unsigned r[4];
                ldsm_x4(smem_u32(&khi[key][d]), r);
                bf[2*np][0] = r[0]; bf[2*np][1] = r[1];
                bf[2*np+1][0] = r[2]; bf[2*np+1][1] = r[3];
            }
            #pragma unroll
            for (int nt = 0; nt < 8; ++nt) mma16816(sacc[nt], qhi[kk], bf[nt]);
            #pragma unroll
            for (int nt = 0; nt < 8; ++nt) mma16816(sacc[nt], qlo[kk], bf[nt]);
            // Klo fragments
            #pragma unroll
            for (int np = 0; np < 4; ++np) {
                const int key = 16 * np + l8 + ((grp & 2) ? 8 : 0);
                const int d   = 16 * kk + ((grp & 1) ? 8 : 0);
                unsigned r[4];
                ldsm_x4(smem_u32(&klo[key][d]), r);
                bf[2*np][0] = r[0]; bf[2*np][1] = r[1];
                bf[2*np+1][0] = r[2]; bf[2*np+1][1] = r[3];
            }
            #pragma unroll
            for (int nt = 0; nt < 8; ++nt) mma16816(sacc[nt], qhi[kk], bf[nt]);
        }

        // ---- stream raw scores (rows g, g+8; cols 8nt + 2qq) ----
        {
            float* s0 = sc + (size_t)(16 * w + g) * N_ + kt * 64;
            float* s1 = s0 + 8 * N_;
            #pragma unroll
            for (int nt = 0; nt < 8; ++nt) {
                *(float2*)(s0 + 8 * nt + 2 * qq) = make_float2(sacc[nt][0], sacc[nt][1]);
                *(float2*)(s1 + 8 * nt + 2 * qq) = make_float2(sacc[nt][2], sacc[nt][3]);
            }
        }

        // ---- online softmax (rows g and g+8, 4 lanes per row) ----
        {
            float mx0 = -INFINITY, mx1 = -INFINITY;
            #pragma unroll
            for (int nt = 0; nt < 8; ++nt) {
                mx0 = fmaxf(mx0, fmaxf(sacc[nt][0], sacc[nt][1]));
                mx1 = fmaxf(mx1, fmaxf(sacc[nt][2], sacc[nt][3]));
            }
            mx0 = fmaxf(mx0, __shfl_xor_sync(0xffffffffu, mx0, 1));
            mx0 = fmaxf(mx0, __shfl_xor_sync(0xffffffffu, mx0, 2));
            mx1 = fmaxf(mx1, __shfl_xor_sync(0xffffffffu, mx1, 1));
            mx1 = fmaxf(mx1, __shfl_xor_sync(0xffffffffu, mx1, 2));
            const float mn0 = fmaxf(m0, mx0), mn1 = fmaxf(m1, mx1);
            const float cr0 = __expf(m0 - mn0), cr1 = __expf(m1 - mn1);
            float rs0 = 0.f, rs1 = 0.f;
            #pragma unroll
            for (int nt = 0; nt < 8; ++nt) {
                sacc[nt][0] = __expf(sacc[nt][0] - mn0);
                sacc[nt][1] = __expf(sacc[nt][1] - mn0);
                sacc[nt][2] = __expf(sacc[nt][2] - mn1);
                sacc[nt][3] = __expf(sacc[nt][3] - mn1);
                rs0 += sacc[nt][0] + sacc[nt][1];
                rs1 += sacc[nt][2] + sacc[nt][3];
            }
            rs0 += __shfl_xor_sync(0xffffffffu, rs0, 1);
            rs0 += __shfl_xor_sync(0xffffffffu, rs0, 2);
            rs1 += __shfl_xor_sync(0xffffffffu, rs1, 1);
            rs1 += __shfl_xor_sync(0xffffffffu, rs1, 2);
            l0 = l0 * cr0 + rs0;  m0 = mn0;
            l1 = l1 * cr1 + rs1;  m1 = mn1;
            #pragma unroll
            for (int nt = 0; nt < 8; ++nt) {
                oacc[nt][0] *= cr0; oacc[nt][1] *= cr0;
                oacc[nt][2] *= cr1; oacc[nt][3] *= cr1;
            }
        }

        // ---- P fragments from S accumulators (FA2 layout identity) ----
        unsigned phi[4][4], plo[4][4];
        #pragma unroll
        for (int ks = 0; ks < 4; ++ks) {
            split2(sacc[2*ks][0],   sacc[2*ks][1],   phi[ks][0], plo[ks][0]);
            split2(sacc[2*ks][2],   sacc[2*ks][3],   phi[ks][1], plo[ks][1]);
            split2(sacc[2*ks+1][0], sacc[2*ks+1][1], phi[ks][2], plo[ks][2]);
            split2(sacc[2*ks+1][2], sacc[2*ks+1][3], phi[ks][3], plo[ks][3]);
        }

        // ---- O += P @ V ----
        #pragma unroll
        for (int ks = 0; ks < 4; ++ks) {
            unsigned bf[8][2];
            // Vhi fragments (trans): n-tiles over d
            #pragma unroll
            for (int np = 0; np < 4; ++np) {
                const int key = 16 * ks + l8 + ((grp & 1) ? 8 : 0);
                const int d   = 16 * np + ((grp & 2) ? 8 : 0);
                unsigned r[4];
                ldsm_x4_t(smem_u32(&vhi[key][d]), r);
                bf[2*np][0] = r[0]; bf[2*np][1] = r[1];
                bf[2*np+1][0] = r[2]; bf[2*np+1][1] = r[3];
            }
            #pragma unroll
            for (int nt = 0; nt < 8; ++nt) mma16816(oacc[nt], phi[ks], bf[nt]);
            #pragma unroll
            for (int nt = 0; nt < 8; ++nt) mma16816(oacc[nt], plo[ks], bf[nt]);
            // Vlo fragments
            #pragma unroll
            for (int np = 0; np < 4; ++np) {
                const int key = 16 * ks + l8 + ((grp & 1) ? 8 : 0);
                const int d   = 16 * np + ((grp & 2) ? 8 : 0);
                unsigned r[4];
                ldsm_x4_t(smem_u32(&vlo[key][d]), r);
                bf[2*np][0] = r[0]; bf[2*np][1] = r[1];
                bf[2*np+1][0] = r[2]; bf[2*np+1][1] = r[3];
            }
            #pragma unroll
            for (int nt = 0; nt < 8; ++nt) mma16816(oacc[nt], phi[ks], bf[nt]);
        }
        __syncthreads();   // all smem reads done before next tile fill
    }

    // ---- finalize: O /= l, write concat-head layout [B,N,256] ----
    const int b = bh >> 2, h = bh & 3;
    const float i0 = 1.f / l0, i1 = 1.f / l1;
    const int n0 = qt * 128 + 16 * w + g;
    float* x0 = g_x + ((size_t)b * N_ + n0) * DM + h * DH;
    float* x1 = x0 + (size_t)8 * DM;
    #pragma unroll
    for (int nt = 0; nt < 8; ++nt) {
        *(float2*)(x0 + 8 * nt + 2 * qq) = make_float2(oacc[nt][0] * i0, oacc[nt][1] * i0);
        *(float2*)(x1 + 8 * nt + 2 * qq) = make_float2(oacc[nt][2] * i1, oacc[nt][3] * i1);
    }
}

// ---------------------------------------------------------------------------
// Kernel 3: out = x @ Wo^T + bo (proven version, unchanged)
// ---------------------------------------------------------------------------
__global__ __launch_bounds__(256) void outproj_kernel(
    float* __restrict__ out, const float* __restrict__ Wo, const float* __restrict__ bo)
{
    const int o0   = blockIdx.y * 64;
    const int row0 = blockIdx.x * 64;
    const int t  = threadIdx.x;
    const int tx = t & 15, ty = t >> 4;

    __shared__ float As[16][64];
    __shared__ float Bs[16][64];

    float acc[4][4];
    #pragma unroll
    for (int r = 0; r < 4; ++r)
        #pragma unroll
        for (int c = 0; c < 4; ++c) acc[r][c] = 0.f;

    for (int k0 = 0; k0 < DM; k0 += 16) {
        {
            const int ar = t >> 2, ac = (t & 3) * 4;
            float4 a4 = *(const float4*)(g_x + (size_t)(row0 + ar) * DM + k0 + ac);
            As[ac + 0][ar] = a4.x; As[ac + 1][ar] = a4.y;
            As[ac + 2][ar] = a4.z; As[ac + 3][ar] = a4.w;
        }
        {
            const int oc = t >> 2, d4 = (t & 3) * 4;
            float4 w = *(const float4*)(Wo + (size_t)(o0 + oc) * DM + k0 + d4);
            Bs[d4 + 0][oc] = w.x; Bs[d4 + 1][oc] = w.y;
            Bs[d4 + 2][oc] = w.z; Bs[d4 + 3][oc] = w.w;
        }
        __syncthreads();
        #pragma unroll
        for (int kk = 0; kk < 16; ++kk) {
            float4 af = *(float4*)&As[kk][ty * 4];
            float4 bf = *(float4*)&Bs[kk][tx * 4];
            float a[4] = {af.x, af.y, af.z, af.w};
            float b[4] = {bf.x, bf.y, bf.z, bf.w};
            #pragma unroll
            for (int r = 0; r < 4; ++r)
                #pragma unroll
                for (int c = 0; c < 4; ++c) acc[r][c] += a[r] * b[c];
        }
        __syncthreads();
    }

    float bias[4];
    #pragma unroll
    for (int c = 0; c < 4; ++c) bias[c] = bo[o0 + tx * 4 + c];
    #pragma unroll
    for (int r = 0; r < 4; ++r) {
        const int row = row0 + ty * 4 + r;
        float4 o = make_float4(acc[r][0] + bias[0], acc[r][1] + bias[1],
                               acc[r][2] + bias[2], acc[r][3] + bias[3]);
        *(float4*)(out + (size_t)row * DM + o0 + tx * 4) = o;
    }
}

// ---------------------------------------------------------------------------
extern "C" void kernel_launch(void* const* d_in, const int* in_sizes, int n_in,
                              void* d_out, int out_size)
{
    const float* Q  = (const float*)d_in[0];
    const float* K  = (const float*)d_in[1];
    const float* V  = (const float*)d_in[2];
    const float* R  = (const float*)d_in[3];
    const float* Wq = (const float*)d_in[4];
    const float* bq = (const float*)d_in[5];
    const float* Wk = (const float*)d_in[6];
    const float* bk = (const float*)d_in[7];
    const float* Wv = (const float*)d_in[8];
    const float* bv = (const float*)d_in[9];
    const float* Wr = (const float*)d_in[10];
    const float* br = (const float*)d_in[11];
    const float* Wo = (const float*)d_in[12];
    const float* bo = (const float*)d_in[13];

    float* out    = (float*)d_out;            // [B,N,256]
    float* scores = out + OUT_ELEMS;          // [B,H,N,N]

    proj_kernel<<<dim3((B_ * N_) / 64, H_, 3), 256>>>(
        Q, K, V, R, Wq, bq, Wk, bk, Wv, bv, Wr, br);

    attn_mma_kernel<<<dim3(N_ / 128, B_ * H_), 256>>>(scores);

    outproj_kernel<<<dim3((B_ * N_) / 64, DM / 64), 256>>>(out, Wo, bo);
}

// round 16
// speedup vs baseline: 2.3322x; 1.1517x over previous
#include <cuda_runtime.h>
#include <cuda_bf16.h>
#include <math.h>

#define B_  8
#define N_  2048
#define H_  4
#define DM  256
#define DH  64
#define OUT_ELEMS ((size_t)B_ * N_ * DM)

// Scratch (device globals: allocation-free rule)
__device__ float g_q [(size_t)B_*H_*N_*DH];   // [B,H,N,64]
__device__ float g_kr[(size_t)B_*H_*N_*DH];   // [B,H,N,64]
__device__ float g_v [(size_t)B_*H_*N_*DH];   // [B,H,N,64]
__device__ float g_x [(size_t)B_*N_*DM];      // [B,N,256]

// ======================= warp-mma helpers (baseline PTX) ====================
__device__ __forceinline__ unsigned smem_u32(const void* p) {
    return (unsigned)__cvta_generic_to_shared(p);
}
__device__ __forceinline__ void mma16816(float* c, const unsigned* a, const unsigned* b) {
    asm volatile(
        "mma.sync.aligned.m16n8k16.row.col.f32.bf16.bf16.f32 "
        "{%0,%1,%2,%3}, {%4,%5,%6,%7}, {%8,%9}, {%0,%1,%2,%3};"
        : "+f"(c[0]), "+f"(c[1]), "+f"(c[2]), "+f"(c[3])
        : "r"(a[0]), "r"(a[1]), "r"(a[2]), "r"(a[3]), "r"(b[0]), "r"(b[1]));
}
__device__ __forceinline__ void ldsm_x4(unsigned addr, unsigned* r) {
    asm volatile("ldmatrix.sync.aligned.m8n8.x4.shared.b16 {%0,%1,%2,%3}, [%4];"
        : "=r"(r[0]), "=r"(r[1]), "=r"(r[2]), "=r"(r[3]) : "r"(addr));
}
__device__ __forceinline__ void ldsm_x4_t(unsigned addr, unsigned* r) {
    asm volatile("ldmatrix.sync.aligned.m8n8.x4.trans.shared.b16 {%0,%1,%2,%3}, [%4];"
        : "=r"(r[0]), "=r"(r[1]), "=r"(r[2]), "=r"(r[3]) : "r"(addr));
}

// fp32 -> bf16 hi + bf16 lo split
__device__ __forceinline__ void split_bf16(float v, unsigned short& h, unsigned short& l) {
    __nv_bfloat16 hb = __float2bfloat16(v);
    __nv_bfloat16 lb = __float2bfloat16(v - __bfloat162float(hb));
    h = __bfloat16_as_ushort(hb);
    l = __bfloat16_as_ushort(lb);
}
__device__ __forceinline__ void split2(float a, float b, unsigned& hi, unsigned& lo) {
    unsigned short ha, la, hb_, lb_;
    split_bf16(a, ha, la);
    split_bf16(b, hb_, lb_);
    hi = (unsigned)ha | ((unsigned)hb_ << 16);
    lo = (unsigned)la | ((unsigned)lb_ << 16);
}
__device__ __forceinline__ void pack8(const float* v, uint4& H, uint4& L) {
    split2(v[0], v[1], H.x, L.x);
    split2(v[2], v[3], H.y, L.y);
    split2(v[4], v[5], H.z, L.z);
    split2(v[6], v[7], H.w, L.w);
}

// ---------------------------------------------------------------------------
// Kernel 1: projections via bf16 hi/lo mma.sync.
//   CTA: 128 rows x 64 cols (one head, one 'which'); 8 warps, 16 rows each.
//   which: 0 -> q = Q@Wq+bq ; 1 -> kr = K@Wk + R@Wr + biases ; 2 -> v
//   K chunked by 32 (2 mma k-steps). W stored n-major in smem (wt[n][k]).
// ---------------------------------------------------------------------------
#define PSTR 40   // smem row stride (elems): 20 banks -> 8-row ldmatrix conflict-free
__global__ __launch_bounds__(256, 2) void proj_mma_kernel(
    const float* __restrict__ Q, const float* __restrict__ K,
    const float* __restrict__ V, const float* __restrict__ R,
    const float* __restrict__ Wq, const float* __restrict__ bq,
    const float* __restrict__ Wk, const float* __restrict__ bk,
    const float* __restrict__ Wv, const float* __restrict__ bv,
    const float* __restrict__ Wr, const float* __restrict__ br)
{
    __shared__ __nv_bfloat16 ahi[128][PSTR], alo[128][PSTR];
    __shared__ __nv_bfloat16 whi[64][PSTR],  wlo[64][PSTR];

    const int which = blockIdx.z;
    const int h     = blockIdx.y;
    const int row0  = blockIdx.x * 128;
    const int t = threadIdx.x;
    const int w = t >> 5, lane = t & 31;
    const int g = lane >> 2, qq = lane & 3;
    const int l8 = lane & 7, grp = lane >> 3;

    const float* A0; const float* W0;
    const float* A1 = nullptr; const float* W1 = nullptr;
    float* Cout;
    if (which == 0)      { A0 = Q; W0 = Wq; Cout = g_q;  }
    else if (which == 1) { A0 = K; W0 = Wk; A1 = R; W1 = Wr; Cout = g_kr; }
    else                 { A0 = V; W0 = Wv; Cout = g_v;  }

    float oacc[8][4];
    #pragma unroll
    for (int nt = 0; nt < 8; ++nt)
        #pragma unroll
        for (int c = 0; c < 4; ++c) oacc[nt][c] = 0.f;

    const int npass = (which == 1) ? 2 : 1;
    for (int pass = 0; pass < npass; ++pass) {
        const float* A = pass ? A1 : A0;
        const float* W = pass ? W1 : W0;
        for (int k0 = 0; k0 < DM; k0 += 32) {
            // fill A chunk [128 rows x 32 k], hi/lo split
            {
                const int row = t >> 1, koff = (t & 1) * 16;
                const float* ap = A + (size_t)(row0 + row) * DM + k0 + koff;
                float buf[8]; uint4 Hh, Ll;
                float4 a = *(const float4*)(ap);
                float4 b = *(const float4*)(ap + 4);
                buf[0]=a.x; buf[1]=a.y; buf[2]=a.z; buf[3]=a.w;
                buf[4]=b.x; buf[5]=b.y; buf[6]=b.z; buf[7]=b.w;
                pack8(buf, Hh, Ll);
                *(uint4*)&ahi[row][koff] = Hh;  *(uint4*)&alo[row][koff] = Ll;
                a = *(const float4*)(ap + 8);
                b = *(const float4*)(ap + 12);
                buf[0]=a.x; buf[1]=a.y; buf[2]=a.z; buf[3]=a.w;
                buf[4]=b.x; buf[5]=b.y; buf[6]=b.z; buf[7]=b.w;
                pack8(buf, Hh, Ll);
                *(uint4*)&ahi[row][koff + 8] = Hh;  *(uint4*)&alo[row][koff + 8] = Ll;
            }
            // fill W chunk transposed: wt[n][k] = W[h][k0+k][n]
            {
                const int n = t >> 2, koff = (t & 3) * 8;
                const float* wp = W + (size_t)h * DM * DH + (size_t)(k0 + koff) * DH + n;
                #pragma unroll
                for (int e = 0; e < 8; ++e) {
                    unsigned short hv, lv;
                    split_bf16(wp[(size_t)e * DH], hv, lv);
                    whi[n][koff + e] = __ushort_as_bfloat16(hv);
                    wlo[n][koff + e] = __ushort_as_bfloat16(lv);
                }
            }
            __syncthreads();

            #pragma unroll
            for (int ks = 0; ks < 2; ++ks) {
                // A fragments (m16k16, row-major)
                const int ar = 16 * w + l8 + ((grp & 1) ? 8 : 0);
                const int ak = 16 * ks + ((grp & 2) ? 8 : 0);
                unsigned afh[4], afl[4];
                ldsm_x4(smem_u32(&ahi[ar][ak]), afh);
                ldsm_x4(smem_u32(&alo[ar][ak]), afl);
                // B fragments: 8 n-tiles from wt (proven attention K-map)
                unsigned bfh[8][2], bfl[8][2];
                #pragma unroll
                for (int np = 0; np < 4; ++np) {
                    const int nrow = 16 * np + l8 + ((grp & 2) ? 8 : 0);
                    const int kcol = 16 * ks + ((grp & 1) ? 8 : 0);
                    unsigned r[4];
                    ldsm_x4(smem_u32(&whi[nrow][kcol]), r);
                    bfh[2*np][0] = r[0]; bfh[2*np][1] = r[1];
                    bfh[2*np+1][0] = r[2]; bfh[2*np+1][1] = r[3];
                    ldsm_x4(smem_u32(&wlo[nrow][kcol]), r);
                    bfl[2*np][0] = r[0]; bfl[2*np][1] = r[1];
                    bfl[2*np+1][0] = r[2]; bfl[2*np+1][1] = r[3];
                }
                #pragma unroll
                for (int nt = 0; nt < 8; ++nt) {
                    mma16816(oacc[nt], afh, bfh[nt]);
                    mma16816(oacc[nt], afl, bfh[nt]);
                    mma16816(oacc[nt], afh, bfl[nt]);
                }
            }
            __syncthreads();
        }
    }

    // bias + store to head-major scratch [B,H,N,64]
    const float* bA = (which == 0) ? bq : (which == 1) ? bk : bv;
    const int r0g = row0 + 16 * w + g;
    #pragma unroll
    for (int half = 0; half < 2; ++half) {
        const int row = r0g + half * 8;
        const int b   = row >> 11;
        const int n   = row & (N_ - 1);
        float* cp = Cout + ((size_t)(b * H_ + h) * N_ + n) * DH;
        #pragma unroll
        for (int nt = 0; nt < 8; ++nt) {
            const int col = 8 * nt + 2 * qq;
            float b0 = bA[h * DH + col], b1 = bA[h * DH + col + 1];
            if (which == 1) { b0 += br[h * DH + col]; b1 += br[h * DH + col + 1]; }
            *(float2*)(cp + col) = make_float2(oacc[nt][2*half] + b0,
                                               oacc[nt][2*half+1] + b1);
        }
    }
}

// ---------------------------------------------------------------------------
// Kernel 2: flash attention via warp-level bf16 mma.sync (proven, unchanged).
// ---------------------------------------------------------------------------
__global__ __launch_bounds__(256, 1) void attn_mma_kernel(float* __restrict__ scores_out)
{
    __shared__ __nv_bfloat16 khi[64][72], klo[64][72];
    __shared__ __nv_bfloat16 vhi[64][72], vlo[64][72];

    const int t = threadIdx.x;
    const int w = t >> 5, lane = t & 31;
    const int g = lane >> 2, qq = lane & 3;
    const int qt = blockIdx.x, bh = blockIdx.y;

    const float* qbase = g_q  + ((size_t)bh * N_ + (size_t)qt * 128 + 16 * w) * DH;
    const float* kbase = g_kr + (size_t)bh * N_ * DH;
    const float* vbase = g_v  + (size_t)bh * N_ * DH;
    float* sc = scores_out + (size_t)bh * N_ * N_ + (size_t)(qt * 128) * N_;

    unsigned qhi[4][4], qlo[4][4];
    {
        const float* r0 = qbase + (size_t)g * DH;
        const float* r1 = qbase + (size_t)(g + 8) * DH;
        #pragma unroll
        for (int kk = 0; kk < 4; ++kk) {
            const int c = 16 * kk + 2 * qq;
            float2 v00 = *(const float2*)(r0 + c);
            float2 v10 = *(const float2*)(r1 + c);
            float2 v01 = *(const float2*)(r0 + c + 8);
            float2 v11 = *(const float2*)(r1 + c + 8);
            split2(v00.x * 0.125f, v00.y * 0.125f, qhi[kk][0], qlo[kk][0]);
            split2(v10.x * 0.125f, v10.y * 0.125f, qhi[kk][1], qlo[kk][1]);
            split2(v01.x * 0.125f, v01.y * 0.125f, qhi[kk][2], qlo[kk][2]);
            split2(v11.x * 0.125f, v11.y * 0.125f, qhi[kk][3], qlo[kk][3]);
        }
    }

    float oacc[8][4];
    #pragma unroll
    for (int nt = 0; nt < 8; ++nt)
        #pragma unroll
        for (int c = 0; c < 4; ++c) oacc[nt][c] = 0.f;
    float m0 = -INFINITY, m1 = -INFINITY, l0 = 0.f, l1 = 0.f;

    for (int kt = 0; kt < N_ / 64; ++kt) {
        {
            const int row = t >> 2, cq = (t & 3) * 16;
            const float* ks = kbase + ((size_t)kt * 64 + row) * DH + cq;
            const float* vs = vbase + ((size_t)kt * 64 + row) * DH + cq;
            float buf[8]; uint4 Hh, Ll;
            #pragma unroll
            for (int half = 0; half < 2; ++half) {
                const int c8 = cq + half * 8;
                float4 a = *(const float4*)(ks + half * 8);
                float4 b = *(const float4*)(ks + half * 8 + 4);
                buf[0]=a.x; buf[1]=a.y; buf[2]=a.z; buf[3]=a.w;
                buf[4]=b.x; buf[5]=b.y; buf[6]=b.z; buf[7]=b.w;
                pack8(buf, Hh, Ll);
                *(uint4*)&khi[row][c8] = Hh;
                *(uint4*)&klo[row][c8] = Ll;
                a = *(const float4*)(vs + half * 8);
                b = *(const float4*)(vs + half * 8 + 4);
                buf[0]=a.x; buf[1]=a.y; buf[2]=a.z; buf[3]=a.w;
                buf[4]=b.x; buf[5]=b.y; buf[6]=b.z; buf[7]=b.w;
                pack8(buf, Hh, Ll);
                *(uint4*)&vhi[row][c8] = Hh;
                *(uint4*)&vlo[row][c8] = Ll;
            }
        }
        __syncthreads();

        float sacc[8][4];
        #pragma unroll
        for (int nt = 0; nt < 8; ++nt)
            #pragma unroll
            for (int c = 0; c < 4; ++c) sacc[nt][c] = 0.f;

        const int l8 = lane & 7, grp = lane >> 3;
        #pragma unroll
        for (int kk = 0; kk < 4; ++kk) {
            unsigned bf[8][2];
            #pragma unroll
            for (int np = 0; np < 4; ++np) {
                const int key = 16 * np + l8 + ((grp & 2) ? 8 : 0);
                const int d   = 16 * kk + ((grp & 1) ? 8 : 0);
                unsigned r[4];
                ldsm_x4(smem_u32(&khi[key][d]), r);
                bf[2*np][0] = r[0]; bf[2*np][1] = r[1];
                bf[2*np+1][0] = r[2]; bf[2*np+1][1] = r[3];
            }
            #pragma unroll
            for (int nt = 0; nt < 8; ++nt) mma16816(sacc[nt], qhi[kk], bf[nt]);
            #pragma unroll
            for (int nt = 0; nt < 8; ++nt) mma16816(sacc[nt], qlo[kk], bf[nt]);
            #pragma unroll
            for (int np = 0; np < 4; ++np) {
                const int key = 16 * np + l8 + ((grp & 2) ? 8 : 0);
                const int d   = 16 * kk + ((grp & 1) ? 8 : 0);
                unsigned r[4];
                ldsm_x4(smem_u32(&klo[key][d]), r);
                bf[2*np][0] = r[0]; bf[2*np][1] = r[1];
                bf[2*np+1][0] = r[2]; bf[2*np+1][1] = r[3];
            }
            #pragma unroll
            for (int nt = 0; nt < 8; ++nt) mma16816(sacc[nt], qhi[kk], bf[nt]);
        }

        {
            float* s0 = sc + (size_t)(16 * w + g) * N_ + kt * 64;
            float* s1 = s0 + 8 * N_;
            #pragma unroll
            for (int nt = 0; nt < 8; ++nt) {
                *(float2*)(s0 + 8 * nt + 2 * qq) = make_float2(sacc[nt][0], sacc[nt][1]);
                *(float2*)(s1 + 8 * nt + 2 * qq) = make_float2(sacc[nt][2], sacc[nt][3]);
            }
        }

        {
            float mx0 = -INFINITY, mx1 = -INFINITY;
            #pragma unroll
            for (int nt = 0; nt < 8; ++nt) {
                mx0 = fmaxf(mx0, fmaxf(sacc[nt][0], sacc[nt][1]));
                mx1 = fmaxf(mx1, fmaxf(sacc[nt][2], sacc[nt][3]));
            }
            mx0 = fmaxf(mx0, __shfl_xor_sync(0xffffffffu, mx0, 1));
            mx0 = fmaxf(mx0, __shfl_xor_sync(0xffffffffu, mx0, 2));
            mx1 = fmaxf(mx1, __shfl_xor_sync(0xffffffffu, mx1, 1));
            mx1 = fmaxf(mx1, __shfl_xor_sync(0xffffffffu, mx1, 2));
            const float mn0 = fmaxf(m0, mx0), mn1 = fmaxf(m1, mx1);
            const float cr0 = __expf(m0 - mn0), cr1 = __expf(m1 - mn1);
            float rs0 = 0.f, rs1 = 0.f;
            #pragma unroll
            for (int nt = 0; nt < 8; ++nt) {
                sacc[nt][0] = __expf(sacc[nt][0] - mn0);
                sacc[nt][1] = __expf(sacc[nt][1] - mn0);
                sacc[nt][2] = __expf(sacc[nt][2] - mn1);
                sacc[nt][3] = __expf(sacc[nt][3] - mn1);
                rs0 += sacc[nt][0] + sacc[nt][1];
                rs1 += sacc[nt][2] + sacc[nt][3];
            }
            rs0 += __shfl_xor_sync(0xffffffffu, rs0, 1);
            rs0 += __shfl_xor_sync(0xffffffffu, rs0, 2);
            rs1 += __shfl_xor_sync(0xffffffffu, rs1, 1);
            rs1 += __shfl_xor_sync(0xffffffffu, rs1, 2);
            l0 = l0 * cr0 + rs0;  m0 = mn0;
            l1 = l1 * cr1 + rs1;  m1 = mn1;
            #pragma unroll
            for (int nt = 0; nt < 8; ++nt) {
                oacc[nt][0] *= cr0; oacc[nt][1] *= cr0;
                oacc[nt][2] *= cr1; oacc[nt][3] *= cr1;
            }
        }

        unsigned phi[4][4], plo[4][4];
        #pragma unroll
        for (int ks = 0; ks < 4; ++ks) {
            split2(sacc[2*ks][0],   sacc[2*ks][1],   phi[ks][0], plo[ks][0]);
            split2(sacc[2*ks][2],   sacc[2*ks][3],   phi[ks][1], plo[ks][1]);
            split2(sacc[2*ks+1][0], sacc[2*ks+1][1], phi[ks][2], plo[ks][2]);
            split2(sacc[2*ks+1][2], sacc[2*ks+1][3], phi[ks][3], plo[ks][3]);
        }

        #pragma unroll
        for (int ks = 0; ks < 4; ++ks) {
            unsigned bf[8][2];
            #pragma unroll
            for (int np = 0; np < 4; ++np) {
                const int key = 16 * ks + l8 + ((grp & 1) ? 8 : 0);
                const int d   = 16 * np + ((grp & 2) ? 8 : 0);
                unsigned r[4];
                ldsm_x4_t(smem_u32(&vhi[key][d]), r);
                bf[2*np][0] = r[0]; bf[2*np][1] = r[1];
                bf[2*np+1][0] = r[2]; bf[2*np+1][1] = r[3];
            }
            #pragma unroll
            for (int nt = 0; nt < 8; ++nt) mma16816(oacc[nt], phi[ks], bf[nt]);
            #pragma unroll
            for (int nt = 0; nt < 8; ++nt) mma16816(oacc[nt], plo[ks], bf[nt]);
            #pragma unroll
            for (int np = 0; np < 4; ++np) {
                const int key = 16 * ks + l8 + ((grp & 1) ? 8 : 0);
                const int d   = 16 * np + ((grp & 2) ? 8 : 0);
                unsigned r[4];
                ldsm_x4_t(smem_u32(&vlo[key][d]), r);
                bf[2*np][0] = r[0]; bf[2*np][1] = r[1];
                bf[2*np+1][0] = r[2]; bf[2*np+1][1] = r[3];
            }
            #pragma unroll
            for (int nt = 0; nt < 8; ++nt) mma16816(oacc[nt], phi[ks], bf[nt]);
        }
        __syncthreads();
    }

    const int b = bh >> 2, h = bh & 3;
    const float i0 = 1.f / l0, i1 = 1.f / l1;
    const int n0 = qt * 128 + 16 * w + g;
    float* x0 = g_x + ((size_t)b * N_ + n0) * DM + h * DH;
    float* x1 = x0 + (size_t)8 * DM;
    #pragma unroll
    for (int nt = 0; nt < 8; ++nt) {
        *(float2*)(x0 + 8 * nt + 2 * qq) = make_float2(oacc[nt][0] * i0, oacc[nt][1] * i0);
        *(float2*)(x1 + 8 * nt + 2 * qq) = make_float2(oacc[nt][2] * i1, oacc[nt][3] * i1);
    }
}

// ---------------------------------------------------------------------------
// Kernel 3: out = x @ Wo^T + bo via bf16 hi/lo mma.sync.
//   Wo is [out][in] (torch Linear) == n-major over the contraction -> direct fill.
//   CTA: 128 rows x 64 out-cols; grid (128, 4).
// ---------------------------------------------------------------------------
__global__ __launch_bounds__(256, 2) void outproj_mma_kernel(
    float* __restrict__ out, const float* __restrict__ Wo, const float* __restrict__ bo)
{
    __shared__ __nv_bfloat16 ahi[128][PSTR], alo[128][PSTR];
    __shared__ __nv_bfloat16 whi[64][PSTR],  wlo[64][PSTR];

    const int o0   = blockIdx.y * 64;
    const int row0 = blockIdx.x * 128;
    const int t = threadIdx.x;
    const int w = t >> 5, lane = t & 31;
    const int g = lane >> 2, qq = lane & 3;
    const int l8 = lane & 7, grp = lane >> 3;

    float oacc[8][4];
    #pragma unroll
    for (int nt = 0; nt < 8; ++nt)
        #pragma unroll
        for (int c = 0; c < 4; ++c) oacc[nt][c] = 0.f;

    for (int k0 = 0; k0 < DM; k0 += 32) {
        // fill A chunk from g_x
        {
            const int row = t >> 1, koff = (t & 1) * 16;
            const float* ap = g_x + (size_t)(row0 + row) * DM + k0 + koff;
            float buf[8]; uint4 Hh, Ll;
            float4 a = *(const float4*)(ap);
            float4 b = *(const float4*)(ap + 4);
            buf[0]=a.x; buf[1]=a.y; buf[2]=a.z; buf[3]=a.w;
            buf[4]=b.x; buf[5]=b.y; buf[6]=b.z; buf[7]=b.w;
            pack8(buf, Hh, Ll);
            *(uint4*)&ahi[row][koff] = Hh;  *(uint4*)&alo[row][koff] = Ll;
            a = *(const float4*)(ap + 8);
            b = *(const float4*)(ap + 12);
            buf[0]=a.x; buf[1]=a.y; buf[2]=a.z; buf[3]=a.w;
            buf[4]=b.x; buf[5]=b.y; buf[6]=b.z; buf[7]=b.w;
            pack8(buf, Hh, Ll);
            *(uint4*)&ahi[row][koff + 8] = Hh;  *(uint4*)&alo[row][koff + 8] = Ll;
        }
        // fill Wo chunk: wt[n][k] = Wo[(o0+n)*DM + k0+k]  (coalesced)
        {
            const int n = t >> 2, koff = (t & 3) * 8;
            const float* wp = Wo + (size_t)(o0 + n) * DM + k0 + koff;
            float buf[8]; uint4 Hh, Ll;
            float4 a = *(const float4*)(wp);
            float4 b = *(const float4*)(wp + 4);
            buf[0]=a.x; buf[1]=a.y; buf[2]=a.z; buf[3]=a.w;
            buf[4]=b.x; buf[5]=b.y; buf[6]=b.z; buf[7]=b.w;
            pack8(buf, Hh, Ll);
            *(uint4*)&whi[n][koff] = Hh;  *(uint4*)&wlo[n][koff] = Ll;
        }
        __syncthreads();

        #pragma unroll
        for (int ks = 0; ks < 2; ++ks) {
            const int ar = 16 * w + l8 + ((grp & 1) ? 8 : 0);
            const int ak = 16 * ks + ((grp & 2) ? 8 : 0);
            unsigned afh[4], afl[4];
            ldsm_x4(smem_u32(&ahi[ar][ak]), afh);
            ldsm_x4(smem_u32(&alo[ar][ak]), afl);
            unsigned bfh[8][2], bfl[8][2];
            #pragma unroll
            for (int np = 0; np < 4; ++np) {
                const int nrow = 16 * np + l8 + ((grp & 2) ? 8 : 0);
                const int kcol = 16 * ks + ((grp & 1) ? 8 : 0);
                unsigned r[4];
                ldsm_x4(smem_u32(&whi[nrow][kcol]), r);
                bfh[2*np][0] = r[0]; bfh[2*np][1] = r[1];
                bfh[2*np+1][0] = r[2]; bfh[2*np+1][1] = r[3];
                ldsm_x4(smem_u32(&wlo[nrow][kcol]), r);
                bfl[2*np][0] = r[0]; bfl[2*np][1] = r[1];
                bfl[2*np+1][0] = r[2]; bfl[2*np+1][1] = r[3];
            }
            #pragma unroll
            for (int nt = 0; nt < 8; ++nt) {
                mma16816(oacc[nt], afh, bfh[nt]);
                mma16816(oacc[nt], afl, bfh[nt]);
                mma16816(oacc[nt], afh, bfl[nt]);
            }
        }
        __syncthreads();
    }

    const int r0g = row0 + 16 * w + g;
    #pragma unroll
    for (int half = 0; half < 2; ++half) {
        const int row = r0g + half * 8;
        float* op = out + (size_t)row * DM + o0;
        #pragma unroll
        for (int nt = 0; nt < 8; ++nt) {
            const int col = 8 * nt + 2 * qq;
            *(float2*)(op + col) = make_float2(
                oacc[nt][2*half]   + bo[o0 + col],
                oacc[nt][2*half+1] + bo[o0 + col + 1]);
        }
    }
}

// ---------------------------------------------------------------------------
extern "C" void kernel_launch(void* const* d_in, const int* in_sizes, int n_in,
                              void* d_out, int out_size)
{
    const float* Q  = (const float*)d_in[0];
    const float* K  = (const float*)d_in[1];
    const float* V  = (const float*)d_in[2];
    const float* R  = (const float*)d_in[3];
    const float* Wq = (const float*)d_in[4];
    const float* bq = (const float*)d_in[5];
    const float* Wk = (const float*)d_in[6];
    const float* bk = (const float*)d_in[7];
    const float* Wv = (const float*)d_in[8];
    const float* bv = (const float*)d_in[9];
    const float* Wr = (const float*)d_in[10];
    const float* br = (const float*)d_in[11];
    const float* Wo = (const float*)d_in[12];
    const float* bo = (const float*)d_in[13];

    float* out    = (float*)d_out;            // [B,N,256]
    float* scores = out + OUT_ELEMS;          // [B,H,N,N]

    proj_mma_kernel<<<dim3((B_ * N_) / 128, H_, 3), 256>>>(
        Q, K, V, R, Wq, bq, Wk, bk, Wv, bv, Wr, br);

    attn_mma_kernel<<<dim3(N_ / 128, B_ * H_), 256>>>(scores);

    outproj_mma_kernel<<<dim3((B_ * N_) / 128, DM / 64), 256>>>(out, Wo, bo);
}

// round 17
// speedup vs baseline: 3.2194x; 1.3804x over previous
#include <cuda_runtime.h>
#include <cuda_bf16.h>
#include <math.h>

#define B_  8
#define N_  2048
#define H_  4
#define DM  256
#define DH  64
#define OUT_ELEMS ((size_t)B_ * N_ * DM)

// Scratch (device globals: allocation-free rule)
__device__ float g_q [(size_t)B_*H_*N_*DH];            // [B,H,N,64] fp32
__device__ float g_x [(size_t)B_*N_*DM];               // [B,N,256]  fp32
__device__ __nv_bfloat16 g_khi[(size_t)B_*H_*N_*DH];   // kr split hi
__device__ __nv_bfloat16 g_klo[(size_t)B_*H_*N_*DH];   // kr split lo
__device__ __nv_bfloat16 g_vhi[(size_t)B_*H_*N_*DH];   // v  split hi
__device__ __nv_bfloat16 g_vlo[(size_t)B_*H_*N_*DH];   // v  split lo

// ======================= warp-mma helpers (baseline PTX) ====================
__device__ __forceinline__ unsigned smem_u32(const void* p) {
    return (unsigned)__cvta_generic_to_shared(p);
}
__device__ __forceinline__ void mma16816(float* c, const unsigned* a, const unsigned* b) {
    asm volatile(
        "mma.sync.aligned.m16n8k16.row.col.f32.bf16.bf16.f32 "
        "{%0,%1,%2,%3}, {%4,%5,%6,%7}, {%8,%9}, {%0,%1,%2,%3};"
        : "+f"(c[0]), "+f"(c[1]), "+f"(c[2]), "+f"(c[3])
        : "r"(a[0]), "r"(a[1]), "r"(a[2]), "r"(a[3]), "r"(b[0]), "r"(b[1]));
}
__device__ __forceinline__ void ldsm_x4(unsigned addr, unsigned* r) {
    asm volatile("ldmatrix.sync.aligned.m8n8.x4.shared.b16 {%0,%1,%2,%3}, [%4];"
        : "=r"(r[0]), "=r"(r[1]), "=r"(r[2]), "=r"(r[3]) : "r"(addr));
}
__device__ __forceinline__ void ldsm_x4_t(unsigned addr, unsigned* r) {
    asm volatile("ldmatrix.sync.aligned.m8n8.x4.trans.shared.b16 {%0,%1,%2,%3}, [%4];"
        : "=r"(r[0]), "=r"(r[1]), "=r"(r[2]), "=r"(r[3]) : "r"(addr));
}
__device__ __forceinline__ void cp_async16(unsigned saddr, const void* gaddr) {
    asm volatile("cp.async.ca.shared.global [%0], [%1], 16;"
                 :: "r"(saddr), "l"(gaddr) : "memory");
}
__device__ __forceinline__ void cp_async_wait_all() {
    asm volatile("cp.async.commit_group;\ncp.async.wait_group 0;" ::: "memory");
}

// fp32 -> bf16 hi + bf16 lo split
__device__ __forceinline__ void split_bf16(float v, unsigned short& h, unsigned short& l) {
    __nv_bfloat16 hb = __float2bfloat16(v);
    __nv_bfloat16 lb = __float2bfloat16(v - __bfloat162float(hb));
    h = __bfloat16_as_ushort(hb);
    l = __bfloat16_as_ushort(lb);
}
__device__ __forceinline__ void split2(float a, float b, unsigned& hi, unsigned& lo) {
    unsigned short ha, la, hb_, lb_;
    split_bf16(a, ha, la);
    split_bf16(b, hb_, lb_);
    hi = (unsigned)ha | ((unsigned)hb_ << 16);
    lo = (unsigned)la | ((unsigned)lb_ << 16);
}
__device__ __forceinline__ void pack8(const float* v, uint4& H, uint4& L) {
    split2(v[0], v[1], H.x, L.x);
    split2(v[2], v[3], H.y, L.y);
    split2(v[4], v[5], H.z, L.z);
    split2(v[6], v[7], H.w, L.w);
}

// ---------------------------------------------------------------------------
// Kernel 1: projections via bf16 hi/lo mma.sync.
//   which: 0 -> q (fp32 out) ; 1 -> kr (bf16 hi/lo out) ; 2 -> v (bf16 hi/lo out)
//   W chunk stored k-major in smem (coalesced fill), B frags via ldsm TRANS
//   using the exact V-map proven in the attention PV stage.
// ---------------------------------------------------------------------------
__global__ __launch_bounds__(256, 2) void proj_mma_kernel(
    const float* __restrict__ Q, const float* __restrict__ K,
    const float* __restrict__ V, const float* __restrict__ R,
    const float* __restrict__ Wq, const float* __restrict__ bq,
    const float* __restrict__ Wk, const float* __restrict__ bk,
    const float* __restrict__ Wv, const float* __restrict__ bv,
    const float* __restrict__ Wr, const float* __restrict__ br)
{
    __shared__ __nv_bfloat16 ahi[128][40], alo[128][40];
    __shared__ __nv_bfloat16 wkhi[32][72], wklo[32][72];

    const int which = blockIdx.z;
    const int h     = blockIdx.y;
    const int row0  = blockIdx.x * 128;
    const int t = threadIdx.x;
    const int w = t >> 5, lane = t & 31;
    const int g = lane >> 2, qq = lane & 3;
    const int l8 = lane & 7, grp = lane >> 3;

    const float* A0; const float* W0;
    const float* A1 = nullptr; const float* W1 = nullptr;
    if (which == 0)      { A0 = Q; W0 = Wq; }
    else if (which == 1) { A0 = K; W0 = Wk; A1 = R; W1 = Wr; }
    else                 { A0 = V; W0 = Wv; }

    float oacc[8][4];
    #pragma unroll
    for (int nt = 0; nt < 8; ++nt)
        #pragma unroll
        for (int c = 0; c < 4; ++c) oacc[nt][c] = 0.f;

    const int npass = (which == 1) ? 2 : 1;
    for (int pass = 0; pass < npass; ++pass) {
        const float* A = pass ? A1 : A0;
        const float* W = pass ? W1 : W0;
        for (int k0 = 0; k0 < DM; k0 += 32) {
            // fill A chunk [128 rows x 32 k], hi/lo split (coalesced)
            {
                const int row = t >> 1, koff = (t & 1) * 16;
                const float* ap = A + (size_t)(row0 + row) * DM + k0 + koff;
                float buf[8]; uint4 Hh, Ll;
                float4 a = *(const float4*)(ap);
                float4 b = *(const float4*)(ap + 4);
                buf[0]=a.x; buf[1]=a.y; buf[2]=a.z; buf[3]=a.w;
                buf[4]=b.x; buf[5]=b.y; buf[6]=b.z; buf[7]=b.w;
                pack8(buf, Hh, Ll);
                *(uint4*)&ahi[row][koff] = Hh;  *(uint4*)&alo[row][koff] = Ll;
                a = *(const float4*)(ap + 8);
                b = *(const float4*)(ap + 12);
                buf[0]=a.x; buf[1]=a.y; buf[2]=a.z; buf[3]=a.w;
                buf[4]=b.x; buf[5]=b.y; buf[6]=b.z; buf[7]=b.w;
                pack8(buf, Hh, Ll);
                *(uint4*)&ahi[row][koff + 8] = Hh;  *(uint4*)&alo[row][koff + 8] = Ll;
            }
            // fill W chunk k-major: wk[k][n] = W[h][k0+k][n]  (coalesced float4)
            {
                const int k = t >> 3, n8 = (t & 7) * 8;
                const float* wp = W + (size_t)h * DM * DH + (size_t)(k0 + k) * DH + n8;
                float buf[8]; uint4 Hh, Ll;
                float4 a = *(const float4*)(wp);
                float4 b = *(const float4*)(wp + 4);
                buf[0]=a.x; buf[1]=a.y; buf[2]=a.z; buf[3]=a.w;
                buf[4]=b.x; buf[5]=b.y; buf[6]=b.z; buf[7]=b.w;
                pack8(buf, Hh, Ll);
                *(uint4*)&wkhi[k][n8] = Hh;  *(uint4*)&wklo[k][n8] = Ll;
            }
            __syncthreads();

            #pragma unroll
            for (int ks = 0; ks < 2; ++ks) {
                // A fragments (m16k16, row-major)
                const int ar = 16 * w + l8 + ((grp & 1) ? 8 : 0);
                const int ak = 16 * ks + ((grp & 2) ? 8 : 0);
                unsigned afh[4], afl[4];
                ldsm_x4(smem_u32(&ahi[ar][ak]), afh);
                ldsm_x4(smem_u32(&alo[ar][ak]), afl);
                // B fragments via TRANS ldsm (proven PV V-map: key->k, d->n)
                unsigned bfh[8][2], bfl[8][2];
                #pragma unroll
                for (int np = 0; np < 4; ++np) {
                    const int krow = 16 * ks + l8 + ((grp & 1) ? 8 : 0);
                    const int ncol = 16 * np + ((grp & 2) ? 8 : 0);
                    unsigned r[4];
                    ldsm_x4_t(smem_u32(&wkhi[krow][ncol]), r);
                    bfh[2*np][0] = r[0]; bfh[2*np][1] = r[1];
                    bfh[2*np+1][0] = r[2]; bfh[2*np+1][1] = r[3];
                    ldsm_x4_t(smem_u32(&wklo[krow][ncol]), r);
                    bfl[2*np][0] = r[0]; bfl[2*np][1] = r[1];
                    bfl[2*np+1][0] = r[2]; bfl[2*np+1][1] = r[3];
                }
                #pragma unroll
                for (int nt = 0; nt < 8; ++nt) {
                    mma16816(oacc[nt], afh, bfh[nt]);
                    mma16816(oacc[nt], afl, bfh[nt]);
                    mma16816(oacc[nt], afh, bfl[nt]);
                }
            }
            __syncthreads();
        }
    }

    // epilogue: bias, then store (fp32 for q; bf16 hi/lo for kr and v)
    const float* bA = (which == 0) ? bq : (which == 1) ? bk : bv;
    const int r0g = row0 + 16 * w + g;
    #pragma unroll
    for (int half = 0; half < 2; ++half) {
        const int row = r0g + half * 8;
        const int b   = row >> 11;
        const int n   = row & (N_ - 1);
        const size_t base = ((size_t)(b * H_ + h) * N_ + n) * DH;
        #pragma unroll
        for (int nt = 0; nt < 8; ++nt) {
            const int col = 8 * nt + 2 * qq;
            float b0 = bA[h * DH + col], b1 = bA[h * DH + col + 1];
            if (which == 1) { b0 += br[h * DH + col]; b1 += br[h * DH + col + 1]; }
            const float v0 = oacc[nt][2*half] + b0;
            const float v1 = oacc[nt][2*half+1] + b1;
            if (which == 0) {
                *(float2*)(g_q + base + col) = make_float2(v0, v1);
            } else {
                unsigned hi, lo;
                split2(v0, v1, hi, lo);
                if (which == 1) {
                    *(unsigned*)&g_khi[base + col] = hi;
                    *(unsigned*)&g_klo[base + col] = lo;
                } else {
                    *(unsigned*)&g_vhi[base + col] = hi;
                    *(unsigned*)&g_vlo[base + col] = lo;
                }
            }
        }
    }
}

// ---------------------------------------------------------------------------
// Kernel 2: flash attention via warp-level bf16 mma.sync (hi/lo split).
//   K/V arrive pre-split in bf16 -> fill is a pure cp.async copy.
// ---------------------------------------------------------------------------
__global__ __launch_bounds__(256, 2) void attn_mma_kernel(float* __restrict__ scores_out)
{
    __shared__ __nv_bfloat16 khi[64][72], klo[64][72];
    __shared__ __nv_bfloat16 vhi[64][72], vlo[64][72];

    const int t = threadIdx.x;
    const int w = t >> 5, lane = t & 31;
    const int g = lane >> 2, qq = lane & 3;
    const int qt = blockIdx.x, bh = blockIdx.y;

    const float* qbase = g_q + ((size_t)bh * N_ + (size_t)qt * 128 + 16 * w) * DH;
    float* sc = scores_out + (size_t)bh * N_ * N_ + (size_t)(qt * 128) * N_;

    // per-thread copy role: array a = t>>6, chunk lane c = t&63
    const int ca = t >> 6, cc = t & 63;
    const __nv_bfloat16* gsrc;
    __nv_bfloat16 (*sdst)[72];
    if (ca == 0)      { gsrc = g_khi; sdst = khi; }
    else if (ca == 1) { gsrc = g_klo; sdst = klo; }
    else if (ca == 2) { gsrc = g_vhi; sdst = vhi; }
    else              { gsrc = g_vlo; sdst = vlo; }
    gsrc += (size_t)bh * N_ * DH;

    // Q fragments (resident): 4 k-steps x 4 regs, hi and lo
    unsigned qhi[4][4], qlo[4][4];
    {
        const float* r0 = qbase + (size_t)g * DH;
        const float* r1 = qbase + (size_t)(g + 8) * DH;
        #pragma unroll
        for (int kk = 0; kk < 4; ++kk) {
            const int c = 16 * kk + 2 * qq;
            float2 v00 = *(const float2*)(r0 + c);
            float2 v10 = *(const float2*)(r1 + c);
            float2 v01 = *(const float2*)(r0 + c + 8);
            float2 v11 = *(const float2*)(r1 + c + 8);
            split2(v00.x * 0.125f, v00.y * 0.125f, qhi[kk][0], qlo[kk][0]);
            split2(v10.x * 0.125f, v10.y * 0.125f, qhi[kk][1], qlo[kk][1]);
            split2(v01.x * 0.125f, v01.y * 0.125f, qhi[kk][2], qlo[kk][2]);
            split2(v11.x * 0.125f, v11.y * 0.125f, qhi[kk][3], qlo[kk][3]);
        }
    }

    float oacc[8][4];
    #pragma unroll
    for (int nt = 0; nt < 8; ++nt)
        #pragma unroll
        for (int c = 0; c < 4; ++c) oacc[nt][c] = 0.f;
    float m0 = -INFINITY, m1 = -INFINITY, l0 = 0.f, l1 = 0.f;

    for (int kt = 0; kt < N_ / 64; ++kt) {
        // ---- pure-copy fill: 8 x 16B cp.async per thread ----
        {
            #pragma unroll
            for (int i = 0; i < 8; ++i) {
                const int chunk = cc + 64 * i;      // 0..511
                const int row = chunk >> 3, seg = chunk & 7;
                cp_async16(smem_u32(&sdst[row][seg * 8]),
                           gsrc + ((size_t)(kt * 64 + row)) * DH + seg * 8);
            }
            cp_async_wait_all();
        }
        __syncthreads();

        float sacc[8][4];
        #pragma unroll
        for (int nt = 0; nt < 8; ++nt)
            #pragma unroll
            for (int c = 0; c < 4; ++c) sacc[nt][c] = 0.f;

        const int l8 = lane & 7, grp = lane >> 3;
        #pragma unroll
        for (int kk = 0; kk < 4; ++kk) {
            unsigned bf[8][2];
            #pragma unroll
            for (int np = 0; np < 4; ++np) {
                const int key = 16 * np + l8 + ((grp & 2) ? 8 : 0);
                const int d   = 16 * kk + ((grp & 1) ? 8 : 0);
                unsigned r[4];
                ldsm_x4(smem_u32(&khi[key][d]), r);
                bf[2*np][0] = r[0]; bf[2*np][1] = r[1];
                bf[2*np+1][0] = r[2]; bf[2*np+1][1] = r[3];
            }
            #pragma unroll
            for (int nt = 0; nt < 8; ++nt) mma16816(sacc[nt], qhi[kk], bf[nt]);
            #pragma unroll
            for (int nt = 0; nt < 8; ++nt) mma16816(sacc[nt], qlo[kk], bf[nt]);
            #pragma unroll
            for (int np = 0; np < 4; ++np) {
                const int key = 16 * np + l8 + ((grp & 2) ? 8 : 0);
                const int d   = 16 * kk + ((grp & 1) ? 8 : 0);
                unsigned r[4];
                ldsm_x4(smem_u32(&klo[key][d]), r);
                bf[2*np][0] = r[0]; bf[2*np][1] = r[1];
                bf[2*np+1][0] = r[2]; bf[2*np+1][1] = r[3];
            }
            #pragma unroll
            for (int nt = 0; nt < 8; ++nt) mma16816(sacc[nt], qhi[kk], bf[nt]);
        }

        // stream raw scores
        {
            float* s0 = sc + (size_t)(16 * w + g) * N_ + kt * 64;
            float* s1 = s0 + 8 * N_;
            #pragma unroll
            for (int nt = 0; nt < 8; ++nt) {
                *(float2*)(s0 + 8 * nt + 2 * qq) = make_float2(sacc[nt][0], sacc[nt][1]);
                *(float2*)(s1 + 8 * nt + 2 * qq) = make_float2(sacc[nt][2], sacc[nt][3]);
            }
        }

        // online softmax
        {
            float mx0 = -INFINITY, mx1 = -INFINITY;
            #pragma unroll
            for (int nt = 0; nt < 8; ++nt) {
                mx0 = fmaxf(mx0, fmaxf(sacc[nt][0], sacc[nt][1]));
                mx1 = fmaxf(mx1, fmaxf(sacc[nt][2], sacc[nt][3]));
            }
            mx0 = fmaxf(mx0, __shfl_xor_sync(0xffffffffu, mx0, 1));
            mx0 = fmaxf(mx0, __shfl_xor_sync(0xffffffffu, mx0, 2));
            mx1 = fmaxf(mx1, __shfl_xor_sync(0xffffffffu, mx1, 1));
            mx1 = fmaxf(mx1, __shfl_xor_sync(0xffffffffu, mx1, 2));
            const float mn0 = fmaxf(m0, mx0), mn1 = fmaxf(m1, mx1);
            const float cr0 = __expf(m0 - mn0), cr1 = __expf(m1 - mn1);
            float rs0 = 0.f, rs1 = 0.f;
            #pragma unroll
            for (int nt = 0; nt < 8; ++nt) {
                sacc[nt][0] = __expf(sacc[nt][0] - mn0);
                sacc[nt][1] = __expf(sacc[nt][1] - mn0);
                sacc[nt][2] = __expf(sacc[nt][2] - mn1);
                sacc[nt][3] = __expf(sacc[nt][3] - mn1);
                rs0 += sacc[nt][0] + sacc[nt][1];
                rs1 += sacc[nt][2] + sacc[nt][3];
            }
            rs0 += __shfl_xor_sync(0xffffffffu, rs0, 1);
            rs0 += __shfl_xor_sync(0xffffffffu, rs0, 2);
            rs1 += __shfl_xor_sync(0xffffffffu, rs1, 1);
            rs1 += __shfl_xor_sync(0xffffffffu, rs1, 2);
            l0 = l0 * cr0 + rs0;  m0 = mn0;
            l1 = l1 * cr1 + rs1;  m1 = mn1;
            #pragma unroll
            for (int nt = 0; nt < 8; ++nt) {
                oacc[nt][0] *= cr0; oacc[nt][1] *= cr0;
                oacc[nt][2] *= cr1; oacc[nt][3] *= cr1;
            }
        }

        // P fragments from S accumulators (FA2 layout identity)
        unsigned phi[4][4], plo[4][4];
        #pragma unroll
        for (int ks = 0; ks < 4; ++ks) {
            split2(sacc[2*ks][0],   sacc[2*ks][1],   phi[ks][0], plo[ks][0]);
            split2(sacc[2*ks][2],   sacc[2*ks][3],   phi[ks][1], plo[ks][1]);
            split2(sacc[2*ks+1][0], sacc[2*ks+1][1], phi[ks][2], plo[ks][2]);
            split2(sacc[2*ks+1][2], sacc[2*ks+1][3], phi[ks][3], plo[ks][3]);
        }

        // O += P @ V
        #pragma unroll
        for (int ks = 0; ks < 4; ++ks) {
            unsigned bf[8][2];
            #pragma unroll
            for (int np = 0; np < 4; ++np) {
                const int key = 16 * ks + l8 + ((grp & 1) ? 8 : 0);
                const int d   = 16 * np + ((grp & 2) ? 8 : 0);
                unsigned r[4];
                ldsm_x4_t(smem_u32(&vhi[key][d]), r);
                bf[2*np][0] = r[0]; bf[2*np][1] = r[1];
                bf[2*np+1][0] = r[2]; bf[2*np+1][1] = r[3];
            }
            #pragma unroll
            for (int nt = 0; nt < 8; ++nt) mma16816(oacc[nt], phi[ks], bf[nt]);
            #pragma unroll
            for (int nt = 0; nt < 8; ++nt) mma16816(oacc[nt], plo[ks], bf[nt]);
            #pragma unroll
            for (int np = 0; np < 4; ++np) {
                const int key = 16 * ks + l8 + ((grp & 1) ? 8 : 0);
                const int d   = 16 * np + ((grp & 2) ? 8 : 0);
                unsigned r[4];
                ldsm_x4_t(smem_u32(&vlo[key][d]), r);
                bf[2*np][0] = r[0]; bf[2*np][1] = r[1];
                bf[2*np+1][0] = r[2]; bf[2*np+1][1] = r[3];
            }
            #pragma unroll
            for (int nt = 0; nt < 8; ++nt) mma16816(oacc[nt], phi[ks], bf[nt]);
        }
        __syncthreads();
    }

    const int b = bh >> 2, h = bh & 3;
    const float i0 = 1.f / l0, i1 = 1.f / l1;
    const int n0 = qt * 128 + 16 * w + g;
    float* x0 = g_x + ((size_t)b * N_ + n0) * DM + h * DH;
    float* x1 = x0 + (size_t)8 * DM;
    #pragma unroll
    for (int nt = 0; nt < 8; ++nt) {
        *(float2*)(x0 + 8 * nt + 2 * qq) = make_float2(oacc[nt][0] * i0, oacc[nt][1] * i0);
        *(float2*)(x1 + 8 * nt + 2 * qq) = make_float2(oacc[nt][2] * i1, oacc[nt][3] * i1);
    }
}

// ---------------------------------------------------------------------------
// Kernel 3: out = x @ Wo^T + bo via bf16 hi/lo mma.sync (proven, unchanged).
// ---------------------------------------------------------------------------
__global__ __launch_bounds__(256, 2) void outproj_mma_kernel(
    float* __restrict__ out, const float* __restrict__ Wo, const float* __restrict__ bo)
{
    __shared__ __nv_bfloat16 ahi[128][40], alo[128][40];
    __shared__ __nv_bfloat16 whi[64][40],  wlo[64][40];

    const int o0   = blockIdx.y * 64;
    const int row0 = blockIdx.x * 128;
    const int t = threadIdx.x;
    const int w = t >> 5, lane = t & 31;
    const int g = lane >> 2, qq = lane & 3;
    const int l8 = lane & 7, grp = lane >> 3;

    float oacc[8][4];
    #pragma unroll
    for (int nt = 0; nt < 8; ++nt)
        #pragma unroll
        for (int c = 0; c < 4; ++c) oacc[nt][c] = 0.f;

    for (int k0 = 0; k0 < DM; k0 += 32) {
        {
            const int row = t >> 1, koff = (t & 1) * 16;
            const float* ap = g_x + (size_t)(row0 + row) * DM + k0 + koff;
            float buf[8]; uint4 Hh, Ll;
            float4 a = *(const float4*)(ap);
            float4 b = *(const float4*)(ap + 4);
            buf[0]=a.x; buf[1]=a.y; buf[2]=a.z; buf[3]=a.w;
            buf[4]=b.x; buf[5]=b.y; buf[6]=b.z; buf[7]=b.w;
            pack8(buf, Hh, Ll);
            *(uint4*)&ahi[row][koff] = Hh;  *(uint4*)&alo[row][koff] = Ll;
            a = *(const float4*)(ap + 8);
            b = *(const float4*)(ap + 12);
            buf[0]=a.x; buf[1]=a.y; buf[2]=a.z; buf[3]=a.w;
            buf[4]=b.x; buf[5]=b.y; buf[6]=b.z; buf[7]=b.w;
            pack8(buf, Hh, Ll);
            *(uint4*)&ahi[row][koff + 8] = Hh;  *(uint4*)&alo[row][koff + 8] = Ll;
        }
        {
            const int n = t >> 2, koff = (t & 3) * 8;
            const float* wp = Wo + (size_t)(o0 + n) * DM + k0 + koff;
            float buf[8]; uint4 Hh, Ll;
            float4 a = *(const float4*)(wp);
            float4 b = *(const float4*)(wp + 4);
            buf[0]=a.x; buf[1]=a.y; buf[2]=a.z; buf[3]=a.w;
            buf[4]=b.x; buf[5]=b.y; buf[6]=b.z; buf[7]=b.w;
            pack8(buf, Hh, Ll);
            *(uint4*)&whi[n][koff] = Hh;  *(uint4*)&wlo[n][koff] = Ll;
        }
        __syncthreads();

        #pragma unroll
        for (int ks = 0; ks < 2; ++ks) {
            const int ar = 16 * w + l8 + ((grp & 1) ? 8 : 0);
            const int ak = 16 * ks + ((grp & 2) ? 8 : 0);
            unsigned afh[4], afl[4];
            ldsm_x4(smem_u32(&ahi[ar][ak]), afh);
            ldsm_x4(smem_u32(&alo[ar][ak]), afl);
            unsigned bfh[8][2], bfl[8][2];
            #pragma unroll
            for (int np = 0; np < 4; ++np) {
                const int nrow = 16 * np + l8 + ((grp & 2) ? 8 : 0);
                const int kcol = 16 * ks + ((grp & 1) ? 8 : 0);
                unsigned r[4];
                ldsm_x4(smem_u32(&whi[nrow][kcol]), r);
                bfh[2*np][0] = r[0]; bfh[2*np][1] = r[1];
                bfh[2*np+1][0] = r[2]; bfh[2*np+1][1] = r[3];
                ldsm_x4(smem_u32(&wlo[nrow][kcol]), r);
                bfl[2*np][0] = r[0]; bfl[2*np][1] = r[1];
                bfl[2*np+1][0] = r[2]; bfl[2*np+1][1] = r[3];
            }
            #pragma unroll
            for (int nt = 0; nt < 8; ++nt) {
                mma16816(oacc[nt], afh, bfh[nt]);
                mma16816(oacc[nt], afl, bfh[nt]);
                mma16816(oacc[nt], afh, bfl[nt]);
            }
        }
        __syncthreads();
    }

    const int r0g = row0 + 16 * w + g;
    #pragma unroll
    for (int half = 0; half < 2; ++half) {
        const int row = r0g + half * 8;
        float* op = out + (size_t)row * DM + o0;
        #pragma unroll
        for (int nt = 0; nt < 8; ++nt) {
            const int col = 8 * nt + 2 * qq;
            *(float2*)(op + col) = make_float2(
                oacc[nt][2*half]   + bo[o0 + col],
                oacc[nt][2*half+1] + bo[o0 + col + 1]);
        }
    }
}

// ---------------------------------------------------------------------------
extern "C" void kernel_launch(void* const* d_in, const int* in_sizes, int n_in,
                              void* d_out, int out_size)
{
    const float* Q  = (const float*)d_in[0];
    const float* K  = (const float*)d_in[1];
    const float* V  = (const float*)d_in[2];
    const float* R  = (const float*)d_in[3];
    const float* Wq = (const float*)d_in[4];
    const float* bq = (const float*)d_in[5];
    const float* Wk = (const float*)d_in[6];
    const float* bk = (const float*)d_in[7];
    const float* Wv = (const float*)d_in[8];
    const float* bv = (const float*)d_in[9];
    const float* Wr = (const float*)d_in[10];
    const float* br = (const float*)d_in[11];
    const float* Wo = (const float*)d_in[12];
    const float* bo = (const float*)d_in[13];

    float* out    = (float*)d_out;            // [B,N,256]
    float* scores = out + OUT_ELEMS;          // [B,H,N,N]

    proj_mma_kernel<<<dim3((B_ * N_) / 128, H_, 3), 256>>>(
        Q, K, V, R, Wq, bq, Wk, bk, Wv, bv, Wr, br);

    attn_mma_kernel<<<dim3(N_ / 128, B_ * H_), 256>>>(scores);

    outproj_mma_kernel<<<dim3((B_ * N_) / 128, DM / 64), 256>>>(out, Wo, bo);
}